// round 2
// baseline (speedup 1.0000x reference)
#include <cuda_runtime.h>
#include <cstdint>

#define DIM 2048
#define HID 1024
#define NEXP 8
#define TOTAL 16384

// 64MB scratch for h = silu(x@G^T) * (x@U^T)
__device__ float g_hbuf[(size_t)TOTAL * HID];

__device__ __forceinline__ uint32_t f2tf32(float x) {
    uint32_t r;
    asm("cvt.rna.tf32.f32 %0, %1;" : "=r"(r) : "f"(x));
    return r;
}

__device__ __forceinline__ void mma_tf32(float c[4], const uint32_t a[4], const uint32_t b[2]) {
    asm volatile(
        "mma.sync.aligned.m16n8k8.row.col.f32.tf32.tf32.f32 "
        "{%0,%1,%2,%3}, {%4,%5,%6,%7}, {%8,%9}, {%0,%1,%2,%3};"
        : "+f"(c[0]), "+f"(c[1]), "+f"(c[2]), "+f"(c[3])
        : "r"(a[0]), "r"(a[1]), "r"(a[2]), "r"(a[3]), "r"(b[0]), "r"(b[1]));
}

__device__ __forceinline__ int expert_of(const int* __restrict__ counts, int row0) {
    int e = 0, acc = 0;
#pragma unroll
    for (int i = 0; i < NEXP; i++) {
        if (row0 >= acc) e = i;
        acc += counts[i];
    }
    return e;
}

// ---------------------------------------------------------------------------
// Fragment-order smem layouts (BK = 32, i.e. 4 k8-chunks).
//
// A tile 128(M) x 32(K), stored so one lane's m16n8k8 A-fragment (4 regs) is a
// single LDS.128:
//   element (r, c): t=r>>4, gid=(r&15)&7, half=(r&15)>>3,
//                   kk8=c>>3, tg=c&3, khalf=(c>>2)&1, lane=gid*4+tg,
//                   q = half + 2*khalf
//   idx = ((kk8*8 + t)*32 + lane)*4 + q          (4096 u32 = 16 KB)
//
// B tile 64(N) x 32(K), one lane's B-fragment (2 regs) = LDS.64:
//   element (rb, c): t=rb>>3, gid=rb&7, kk8=c>>3, tg=c&3, khalf=(c>>2)&1
//   idx = ((kk8*8 + t)*32 + gid*4+tg)*2 + khalf  (2048 u32 = 8 KB)
// ---------------------------------------------------------------------------

// store one float4 (row r, cols c..c+3, c%4==0) of an A tile into frag layout
__device__ __forceinline__ void stA(uint32_t* As, int r, int c, float4 v) {
    int t = r >> 4, rl = r & 15, gid = rl & 7, half = rl >> 3;
    int kk8 = c >> 3, khalf = (c >> 2) & 1;
    int q = half + 2 * khalf;
    int base = ((kk8 * 8 + t) * 32 + gid * 4) * 4 + q;
    As[base     ] = f2tf32(v.x);
    As[base +  4] = f2tf32(v.y);
    As[base +  8] = f2tf32(v.z);
    As[base + 12] = f2tf32(v.w);
}
// store one float4 (row rb, cols c..c+3) of a B tile into frag layout
__device__ __forceinline__ void stB(uint32_t* Bs, int rb, int c, float4 v) {
    int t = rb >> 3, gid = rb & 7;
    int kk8 = c >> 3, khalf = (c >> 2) & 1;
    int base = ((kk8 * 8 + t) * 32 + gid * 4) * 2 + khalf;
    Bs[base    ] = f2tf32(v.x);
    Bs[base + 2] = f2tf32(v.y);
    Bs[base + 4] = f2tf32(v.z);
    Bs[base + 6] = f2tf32(v.w);
}

// ---------------------------------------------------------------------------
// Kernel 1: fused gate+up GEMM + SwiGLU. BM=128, BN=64, BK=32, 8 warps (4x2),
// warp tile 32x32 per matrix.
// ---------------------------------------------------------------------------
__global__ __launch_bounds__(256) void gateup_kernel(
    const float* __restrict__ x,
    const float* __restrict__ gate,
    const float* __restrict__ up,
    const int* __restrict__ counts)
{
    __shared__ __align__(16) uint32_t As[4096];
    __shared__ __align__(16) uint32_t Gs[2048];
    __shared__ __align__(16) uint32_t Us[2048];

    const int tid  = threadIdx.x;
    const int lane = tid & 31;
    const int warp = tid >> 5;
    const int gid  = lane >> 2;
    const int tg   = lane & 3;
    const int wm   = (warp >> 1) * 32;
    const int wn   = (warp & 1) * 32;

    const int row0 = blockIdx.y * 128;
    const int n0   = blockIdx.x * 64;
    const int e = expert_of(counts, row0);

    const float* Ap = x    + (size_t)row0 * DIM;
    const float* Gp = gate + (size_t)e * HID * DIM + (size_t)n0 * DIM;
    const float* Up = up   + (size_t)e * HID * DIM + (size_t)n0 * DIM;

    float4 ra[4], rg[2], ru[2];

    auto loadg = [&](int k0) {
#pragma unroll
        for (int i = 0; i < 4; i++) {
            int f = i * 256 + tid; int r = f >> 3; int c = (f & 7) * 4;
            ra[i] = *reinterpret_cast<const float4*>(Ap + (size_t)r * DIM + k0 + c);
        }
#pragma unroll
        for (int i = 0; i < 2; i++) {
            int f = i * 256 + tid; int r = f >> 3; int c = (f & 7) * 4;
            rg[i] = *reinterpret_cast<const float4*>(Gp + (size_t)r * DIM + k0 + c);
            ru[i] = *reinterpret_cast<const float4*>(Up + (size_t)r * DIM + k0 + c);
        }
    };
    auto stores = [&]() {
#pragma unroll
        for (int i = 0; i < 4; i++) {
            int f = i * 256 + tid; int r = f >> 3; int c = (f & 7) * 4;
            stA(As, r, c, ra[i]);
        }
#pragma unroll
        for (int i = 0; i < 2; i++) {
            int f = i * 256 + tid; int r = f >> 3; int c = (f & 7) * 4;
            stB(Gs, r, c, rg[i]);
            stB(Us, r, c, ru[i]);
        }
    };

    float accg[2][4][4] = {};
    float accu[2][4][4] = {};

    loadg(0);
    stores();
    __syncthreads();

    const int NK = DIM / 32;
    for (int kt = 0; kt < NK; kt++) {
        if (kt + 1 < NK) loadg((kt + 1) * 32);

#pragma unroll
        for (int kk8 = 0; kk8 < 4; kk8++) {
            uint32_t af[2][4];
#pragma unroll
            for (int mi = 0; mi < 2; mi++) {
                int t = (wm >> 4) + mi;
                uint4 v = *reinterpret_cast<const uint4*>(&As[((kk8 * 8 + t) * 32 + lane) * 4]);
                af[mi][0] = v.x; af[mi][1] = v.y; af[mi][2] = v.z; af[mi][3] = v.w;
            }
#pragma unroll
            for (int ni = 0; ni < 4; ni++) {
                int t = (wn >> 3) + ni;
                uint2 vg = *reinterpret_cast<const uint2*>(&Gs[((kk8 * 8 + t) * 32 + lane) * 2]);
                uint2 vu = *reinterpret_cast<const uint2*>(&Us[((kk8 * 8 + t) * 32 + lane) * 2]);
                uint32_t bg[2] = {vg.x, vg.y};
                uint32_t bu[2] = {vu.x, vu.y};
#pragma unroll
                for (int mi = 0; mi < 2; mi++) {
                    mma_tf32(accg[mi][ni], af[mi], bg);
                    mma_tf32(accu[mi][ni], af[mi], bu);
                }
            }
        }
        __syncthreads();
        if (kt + 1 < NK) {
            stores();
            __syncthreads();
        }
    }

#pragma unroll
    for (int mi = 0; mi < 2; mi++)
#pragma unroll
        for (int ni = 0; ni < 4; ni++)
#pragma unroll
            for (int q = 0; q < 4; q++) {
                int r = wm + mi * 16 + gid + ((q >= 2) ? 8 : 0);
                int c = wn + ni * 8 + tg * 2 + (q & 1);
                float g = accg[mi][ni][q];
                float u = accu[mi][ni][q];
                float h = g * u / (1.0f + __expf(-g));
                g_hbuf[(size_t)(row0 + r) * HID + (n0 + c)] = h;
            }
}

// ---------------------------------------------------------------------------
// Kernel 2: down GEMM. out = h @ D_e^T. M=16384, N=2048, K=1024.
// ---------------------------------------------------------------------------
__global__ __launch_bounds__(256) void down_kernel(
    const float* __restrict__ down,
    const int* __restrict__ counts,
    float* __restrict__ out)
{
    __shared__ __align__(16) uint32_t As[4096];
    __shared__ __align__(16) uint32_t Ds[2048];

    const int tid  = threadIdx.x;
    const int lane = tid & 31;
    const int warp = tid >> 5;
    const int gid  = lane >> 2;
    const int tg   = lane & 3;
    const int wm   = (warp >> 1) * 32;
    const int wn   = (warp & 1) * 32;

    const int row0 = blockIdx.y * 128;
    const int n0   = blockIdx.x * 64;
    const int e = expert_of(counts, row0);

    const float* Ap = g_hbuf + (size_t)row0 * HID;
    const float* Dp = down   + (size_t)e * DIM * HID + (size_t)n0 * HID;

    float4 ra[4], rd[2];

    auto loadg = [&](int k0) {
#pragma unroll
        for (int i = 0; i < 4; i++) {
            int f = i * 256 + tid; int r = f >> 3; int c = (f & 7) * 4;
            ra[i] = *reinterpret_cast<const float4*>(Ap + (size_t)r * HID + k0 + c);
        }
#pragma unroll
        for (int i = 0; i < 2; i++) {
            int f = i * 256 + tid; int r = f >> 3; int c = (f & 7) * 4;
            rd[i] = *reinterpret_cast<const float4*>(Dp + (size_t)r * HID + k0 + c);
        }
    };
    auto stores = [&]() {
#pragma unroll
        for (int i = 0; i < 4; i++) {
            int f = i * 256 + tid; int r = f >> 3; int c = (f & 7) * 4;
            stA(As, r, c, ra[i]);
        }
#pragma unroll
        for (int i = 0; i < 2; i++) {
            int f = i * 256 + tid; int r = f >> 3; int c = (f & 7) * 4;
            stB(Ds, r, c, rd[i]);
        }
    };

    float acc[2][4][4] = {};

    loadg(0);
    stores();
    __syncthreads();

    const int NK = HID / 32;
    for (int kt = 0; kt < NK; kt++) {
        if (kt + 1 < NK) loadg((kt + 1) * 32);

#pragma unroll
        for (int kk8 = 0; kk8 < 4; kk8++) {
            uint32_t af[2][4];
#pragma unroll
            for (int mi = 0; mi < 2; mi++) {
                int t = (wm >> 4) + mi;
                uint4 v = *reinterpret_cast<const uint4*>(&As[((kk8 * 8 + t) * 32 + lane) * 4]);
                af[mi][0] = v.x; af[mi][1] = v.y; af[mi][2] = v.z; af[mi][3] = v.w;
            }
#pragma unroll
            for (int ni = 0; ni < 4; ni++) {
                int t = (wn >> 3) + ni;
                uint2 vd = *reinterpret_cast<const uint2*>(&Ds[((kk8 * 8 + t) * 32 + lane) * 2]);
                uint32_t bd[2] = {vd.x, vd.y};
#pragma unroll
                for (int mi = 0; mi < 2; mi++) {
                    mma_tf32(acc[mi][ni], af[mi], bd);
                }
            }
        }
        __syncthreads();
        if (kt + 1 < NK) {
            stores();
            __syncthreads();
        }
    }

#pragma unroll
    for (int mi = 0; mi < 2; mi++)
#pragma unroll
        for (int ni = 0; ni < 4; ni++)
#pragma unroll
            for (int q = 0; q < 4; q++) {
                int r = wm + mi * 16 + gid + ((q >= 2) ? 8 : 0);
                int c = wn + ni * 8 + tg * 2 + (q & 1);
                out[(size_t)(row0 + r) * DIM + (n0 + c)] = acc[mi][ni][q];
            }
}

extern "C" void kernel_launch(void* const* d_in, const int* in_sizes, int n_in,
                              void* d_out, int out_size) {
    const float* x      = (const float*)d_in[0];
    const float* gate   = (const float*)d_in[1];
    const float* up     = (const float*)d_in[2];
    const float* down   = (const float*)d_in[3];
    const int*   counts = (const int*)d_in[4];
    float* out = (float*)d_out;

    dim3 g1(HID / 64, TOTAL / 128);   // (16, 128)
    gateup_kernel<<<g1, 256>>>(x, gate, up, counts);

    dim3 g2(DIM / 64, TOTAL / 128);   // (32, 128)
    down_kernel<<<g2, 256>>>(down, counts, out);
}

// round 3
// speedup vs baseline: 1.6807x; 1.6807x over previous
#include <cuda_runtime.h>
#include <cstdint>

#define DIM 2048
#define HID 1024
#define NEXP 8
#define TOTAL 16384
#define LDA 36   // padded u32 stride (conflict-free, 16B-aligned)

// 64MB scratch for h = silu(x@G^T) * (x@U^T)
__device__ float g_hbuf[(size_t)TOTAL * HID];

__device__ __forceinline__ uint32_t f2tf32(float x) {
    uint32_t r;
    asm("cvt.rna.tf32.f32 %0, %1;" : "=r"(r) : "f"(x));
    return r;
}

__device__ __forceinline__ void mma_tf32(float c[4], const uint32_t a[4], const uint32_t b[2]) {
    asm volatile(
        "mma.sync.aligned.m16n8k8.row.col.f32.tf32.tf32.f32 "
        "{%0,%1,%2,%3}, {%4,%5,%6,%7}, {%8,%9}, {%0,%1,%2,%3};"
        : "+f"(c[0]), "+f"(c[1]), "+f"(c[2]), "+f"(c[3])
        : "r"(a[0]), "r"(a[1]), "r"(a[2]), "r"(a[3]), "r"(b[0]), "r"(b[1]));
}

__device__ __forceinline__ int expert_of(const int* __restrict__ counts, int row0) {
    int e = 0, acc = 0;
#pragma unroll
    for (int i = 0; i < NEXP; i++) {
        if (row0 >= acc) e = i;
        acc += counts[i];
    }
    return e;
}

__device__ __forceinline__ void st_cvt4(uint32_t* dst, float4 v) {
    uint4 w = make_uint4(f2tf32(v.x), f2tf32(v.y), f2tf32(v.z), f2tf32(v.w));
    *reinterpret_cast<uint4*>(dst) = w;
}

// ---------------------------------------------------------------------------
// Kernel 1: fused gate+up + SwiGLU. BM=128, BN=64 (per matrix), BK=32.
// 8 warps (4M x 2N), warp tile 32x32 per matrix (mi=2, ni=4).
// Double-buffered dynamic smem: per buf A 128x36, G 64x36, U 64x36 (u32).
// ---------------------------------------------------------------------------
#define GU_BUF (128*LDA + 64*LDA + 64*LDA)   // 9216 u32 per buffer
__global__ __launch_bounds__(256) void gateup_kernel(
    const float* __restrict__ x,
    const float* __restrict__ gate,
    const float* __restrict__ up,
    const int* __restrict__ counts)
{
    extern __shared__ uint32_t sm[];

    const int tid  = threadIdx.x;
    const int lane = tid & 31;
    const int warp = tid >> 5;
    const int gid  = lane >> 2;
    const int tg   = lane & 3;
    const int wm   = (warp >> 1) * 32;
    const int wn   = (warp & 1) * 32;

    const int row0 = blockIdx.y * 128;
    const int n0   = blockIdx.x * 64;
    const int e = expert_of(counts, row0);

    const float* Ap = x    + (size_t)row0 * DIM;
    const float* Gp = gate + (size_t)e * HID * DIM + (size_t)n0 * DIM;
    const float* Up = up   + (size_t)e * HID * DIM + (size_t)n0 * DIM;

    float4 ra[4], rg[2], ru[2];

    auto gload = [&](int k0) {
#pragma unroll
        for (int i = 0; i < 4; i++) {
            int f = i * 256 + tid; int r = f >> 3; int c = (f & 7) * 4;
            ra[i] = *reinterpret_cast<const float4*>(Ap + (size_t)r * DIM + k0 + c);
        }
#pragma unroll
        for (int i = 0; i < 2; i++) {
            int f = i * 256 + tid; int r = f >> 3; int c = (f & 7) * 4;
            rg[i] = *reinterpret_cast<const float4*>(Gp + (size_t)r * DIM + k0 + c);
            ru[i] = *reinterpret_cast<const float4*>(Up + (size_t)r * DIM + k0 + c);
        }
    };
    auto stage = [&](int buf) {
        uint32_t* As = sm + buf * GU_BUF;
        uint32_t* Gs = As + 128 * LDA;
        uint32_t* Us = Gs + 64 * LDA;
#pragma unroll
        for (int i = 0; i < 4; i++) {
            int f = i * 256 + tid; int r = f >> 3; int c = (f & 7) * 4;
            st_cvt4(&As[r * LDA + c], ra[i]);
        }
#pragma unroll
        for (int i = 0; i < 2; i++) {
            int f = i * 256 + tid; int r = f >> 3; int c = (f & 7) * 4;
            st_cvt4(&Gs[r * LDA + c], rg[i]);
            st_cvt4(&Us[r * LDA + c], ru[i]);
        }
    };

    float accg[2][4][4] = {};
    float accu[2][4][4] = {};

    gload(0);
    stage(0);
    __syncthreads();

    const int NK = DIM / 32;
    for (int kt = 0; kt < NK; kt++) {
        if (kt + 1 < NK) gload((kt + 1) * 32);

        const uint32_t* As = sm + (kt & 1) * GU_BUF;
        const uint32_t* Gs = As + 128 * LDA;
        const uint32_t* Us = Gs + 64 * LDA;
#pragma unroll
        for (int kk8 = 0; kk8 < 4; kk8++) {
            const int kk = kk8 * 8;
            uint32_t af[2][4];
#pragma unroll
            for (int mi = 0; mi < 2; mi++) {
                int r = wm + mi * 16 + gid;
                af[mi][0] = As[r * LDA + kk + tg];
                af[mi][1] = As[(r + 8) * LDA + kk + tg];
                af[mi][2] = As[r * LDA + kk + tg + 4];
                af[mi][3] = As[(r + 8) * LDA + kk + tg + 4];
            }
#pragma unroll
            for (int ni = 0; ni < 4; ni++) {
                int rb = wn + ni * 8 + gid;
                uint32_t bg[2] = { Gs[rb * LDA + kk + tg], Gs[rb * LDA + kk + tg + 4] };
                uint32_t bu[2] = { Us[rb * LDA + kk + tg], Us[rb * LDA + kk + tg + 4] };
#pragma unroll
                for (int mi = 0; mi < 2; mi++) {
                    mma_tf32(accg[mi][ni], af[mi], bg);
                    mma_tf32(accu[mi][ni], af[mi], bu);
                }
            }
        }
        if (kt + 1 < NK) stage((kt + 1) & 1);
        __syncthreads();
    }

    // SwiGLU epilogue, float2 stores
#pragma unroll
    for (int mi = 0; mi < 2; mi++)
#pragma unroll
        for (int ni = 0; ni < 4; ni++) {
            int r = row0 + wm + mi * 16 + gid;
            int c = n0 + wn + ni * 8 + tg * 2;
            float g0 = accg[mi][ni][0], u0 = accu[mi][ni][0];
            float g1 = accg[mi][ni][1], u1 = accu[mi][ni][1];
            float g2 = accg[mi][ni][2], u2 = accu[mi][ni][2];
            float g3 = accg[mi][ni][3], u3 = accu[mi][ni][3];
            float2 h0 = make_float2(g0 * u0 / (1.0f + __expf(-g0)),
                                    g1 * u1 / (1.0f + __expf(-g1)));
            float2 h1 = make_float2(g2 * u2 / (1.0f + __expf(-g2)),
                                    g3 * u3 / (1.0f + __expf(-g3)));
            *reinterpret_cast<float2*>(&g_hbuf[(size_t)r * HID + c]) = h0;
            *reinterpret_cast<float2*>(&g_hbuf[(size_t)(r + 8) * HID + c]) = h1;
        }
}

// ---------------------------------------------------------------------------
// Kernel 2: down GEMM. out = h @ D_e^T. M=16384, N=2048, K=1024.
// BM=128, BN=128, BK=32. 8 warps (2M x 4N), warp tile 64x32 (mi=4, ni=4).
// ---------------------------------------------------------------------------
#define DN_BUF (128*LDA + 128*LDA)   // 9216 u32 per buffer
__global__ __launch_bounds__(256) void down_kernel(
    const float* __restrict__ down,
    const int* __restrict__ counts,
    float* __restrict__ out)
{
    extern __shared__ uint32_t sm[];

    const int tid  = threadIdx.x;
    const int lane = tid & 31;
    const int warp = tid >> 5;
    const int gid  = lane >> 2;
    const int tg   = lane & 3;
    const int wm   = (warp >> 2) * 64;
    const int wn   = (warp & 3) * 32;

    const int row0 = blockIdx.y * 128;
    const int n0   = blockIdx.x * 128;
    const int e = expert_of(counts, row0);

    const float* Ap = g_hbuf + (size_t)row0 * HID;
    const float* Dp = down   + (size_t)e * DIM * HID + (size_t)n0 * HID;

    float4 ra[4], rd[4];

    auto gload = [&](int k0) {
#pragma unroll
        for (int i = 0; i < 4; i++) {
            int f = i * 256 + tid; int r = f >> 3; int c = (f & 7) * 4;
            ra[i] = *reinterpret_cast<const float4*>(Ap + (size_t)r * HID + k0 + c);
            rd[i] = *reinterpret_cast<const float4*>(Dp + (size_t)r * HID + k0 + c);
        }
    };
    auto stage = [&](int buf) {
        uint32_t* As = sm + buf * DN_BUF;
        uint32_t* Ds = As + 128 * LDA;
#pragma unroll
        for (int i = 0; i < 4; i++) {
            int f = i * 256 + tid; int r = f >> 3; int c = (f & 7) * 4;
            st_cvt4(&As[r * LDA + c], ra[i]);
            st_cvt4(&Ds[r * LDA + c], rd[i]);
        }
    };

    float acc[4][4][4] = {};

    gload(0);
    stage(0);
    __syncthreads();

    const int NK = HID / 32;
    for (int kt = 0; kt < NK; kt++) {
        if (kt + 1 < NK) gload((kt + 1) * 32);

        const uint32_t* As = sm + (kt & 1) * DN_BUF;
        const uint32_t* Ds = As + 128 * LDA;
#pragma unroll
        for (int kk8 = 0; kk8 < 4; kk8++) {
            const int kk = kk8 * 8;
            uint32_t af[4][4];
#pragma unroll
            for (int mi = 0; mi < 4; mi++) {
                int r = wm + mi * 16 + gid;
                af[mi][0] = As[r * LDA + kk + tg];
                af[mi][1] = As[(r + 8) * LDA + kk + tg];
                af[mi][2] = As[r * LDA + kk + tg + 4];
                af[mi][3] = As[(r + 8) * LDA + kk + tg + 4];
            }
#pragma unroll
            for (int ni = 0; ni < 4; ni++) {
                int rb = wn + ni * 8 + gid;
                uint32_t bd[2] = { Ds[rb * LDA + kk + tg], Ds[rb * LDA + kk + tg + 4] };
#pragma unroll
                for (int mi = 0; mi < 4; mi++) {
                    mma_tf32(acc[mi][ni], af[mi], bd);
                }
            }
        }
        if (kt + 1 < NK) stage((kt + 1) & 1);
        __syncthreads();
    }

#pragma unroll
    for (int mi = 0; mi < 4; mi++)
#pragma unroll
        for (int ni = 0; ni < 4; ni++) {
            int r = row0 + wm + mi * 16 + gid;
            int c = n0 + wn + ni * 8 + tg * 2;
            *reinterpret_cast<float2*>(&out[(size_t)r * DIM + c]) =
                make_float2(acc[mi][ni][0], acc[mi][ni][1]);
            *reinterpret_cast<float2*>(&out[(size_t)(r + 8) * DIM + c]) =
                make_float2(acc[mi][ni][2], acc[mi][ni][3]);
        }
}

extern "C" void kernel_launch(void* const* d_in, const int* in_sizes, int n_in,
                              void* d_out, int out_size) {
    const float* x      = (const float*)d_in[0];
    const float* gate   = (const float*)d_in[1];
    const float* up     = (const float*)d_in[2];
    const float* down   = (const float*)d_in[3];
    const int*   counts = (const int*)d_in[4];
    float* out = (float*)d_out;

    const int gu_smem = 2 * GU_BUF * 4;   // 73728 B
    const int dn_smem = 2 * DN_BUF * 4;   // 73728 B

    static bool attr_set = false;
    if (!attr_set) {
        cudaFuncSetAttribute(gateup_kernel, cudaFuncAttributeMaxDynamicSharedMemorySize, gu_smem);
        cudaFuncSetAttribute(down_kernel,   cudaFuncAttributeMaxDynamicSharedMemorySize, dn_smem);
        attr_set = true;
    }

    dim3 g1(HID / 64, TOTAL / 128);    // (16, 128)
    gateup_kernel<<<g1, 256, gu_smem>>>(x, gate, up, counts);

    dim3 g2(DIM / 128, TOTAL / 128);   // (16, 128)
    down_kernel<<<g2, 256, dn_smem>>>(down, counts, out);
}